// round 6
// baseline (speedup 1.0000x reference)
#include <cuda_runtime.h>
#include <cuda_bf16.h>
#include <math.h>

#define NATOMS 50000
#define NEDGE  600000
#define HDIM   128
#define NGAUSS 50
#define NLAYER 6
#define NCONF  500
#define NMOL   100
#define TTAB   8192
#define DCUT   13.0f

// ------------------- static device scratch (no allocs allowed) -------------------
__device__ float g_h[NATOMS * HDIM];
__device__ float g_xf[NATOMS * HDIM];
__device__ float g_agg[NATOMS * HDIM];
__device__ float g_U[NLAYER * TTAB * HDIM];    // ssp(gauss@w1+b1)
__device__ float g_tab[NLAYER * TTAB * HDIM];  // W table (incl. cosine cutoff)
__device__ float g_t[NEDGE];                   // table position per edge, -1 = inactive
__device__ int   g_cnt[NATOMS];
__device__ int   g_rowptr[NATOMS + 1];
__device__ int   g_cursor[NATOMS];
__device__ int   g_src[NEDGE];
__device__ float g_et[NEDGE];
__device__ float g_mol[NMOL * HDIM];

__device__ __forceinline__ float sspf(float x) {
    return fmaxf(x, 0.0f) + log1pf(expf(-fabsf(x))) - 0.69314718055994531f;
}

__device__ __forceinline__ unsigned f2tf(float f) {
    unsigned r;
    asm("cvt.rna.tf32.f32 %0, %1;" : "=r"(r) : "f"(f));
    return r;
}

// ------------------- embedding gather -------------------
__global__ void k_embed(const int* __restrict__ z, const float* __restrict__ emb,
                        float* __restrict__ h) {
    int idx = blockIdx.x * blockDim.x + threadIdx.x;
    if (idx >= NATOMS * HDIM) return;
    int a = idx >> 7, f = idx & 127;
    h[idx] = emb[z[a] * HDIM + f];
}

// ------------------- edge distances + histogram -------------------
__global__ void k_dist(const float* __restrict__ pos, const int* __restrict__ erow,
                       const int* __restrict__ ecol, float* __restrict__ tpos,
                       int* __restrict__ cnt) {
    int e = blockIdx.x * blockDim.x + threadIdx.x;
    if (e >= NEDGE) return;
    int r = erow[e], c = ecol[e];
    float dx = pos[r * 3 + 0] - pos[c * 3 + 0];
    float dy = pos[r * 3 + 1] - pos[c * 3 + 1];
    float dz = pos[r * 3 + 2] - pos[c * 3 + 2];
    float d = sqrtf(dx * dx + dy * dy + dz * dz);
    if (d < DCUT) {
        tpos[e] = d * ((float)(TTAB - 1) / DCUT);
        atomicAdd(&cnt[c], 1);
    } else {
        tpos[e] = -1.0f;
    }
}

// ------------------- single-block exclusive scan over N counts -------------------
__global__ void k_scan(const int* __restrict__ cnt, int* __restrict__ rowptr,
                       int* __restrict__ cursor) {
    __shared__ int sm[1024];
    __shared__ int base_s;
    int tid = threadIdx.x;
    if (tid == 0) base_s = 0;
    __syncthreads();
    for (int c0 = 0; c0 < NATOMS; c0 += 1024) {
        int i = c0 + tid;
        int v = (i < NATOMS) ? cnt[i] : 0;
        sm[tid] = v;
        __syncthreads();
        for (int off = 1; off < 1024; off <<= 1) {
            int t = (tid >= off) ? sm[tid - off] : 0;
            __syncthreads();
            sm[tid] += t;
            __syncthreads();
        }
        int incl = sm[tid];
        int base = base_s;
        if (i < NATOMS) {
            int ex = base + incl - v;
            rowptr[i] = ex;
            cursor[i] = ex;
        }
        __syncthreads();
        if (tid == 1023) base_s = base + incl;
        __syncthreads();
    }
    if (tid == 0) rowptr[NATOMS] = base_s;
}

// ------------------- CSR fill -------------------
__global__ void k_fill(const int* __restrict__ erow, const int* __restrict__ ecol,
                       const float* __restrict__ tpos, int* __restrict__ cursor,
                       int* __restrict__ src, float* __restrict__ et) {
    int e = blockIdx.x * blockDim.x + threadIdx.x;
    if (e >= NEDGE) return;
    float t = tpos[e];
    if (t >= 0.0f) {
        int c = ecol[e];
        int p = atomicAdd(&cursor[c], 1);
        src[p] = erow[e];
        et[p] = t;
    }
}

// ------------------- filter table stage1: U = ssp(gauss @ w1 + b1) -------------------
#define S1ROWS 16
__global__ void k_stage1(const float* __restrict__ mlp_w1, const float* __restrict__ mlp_b1,
                         float* __restrict__ U) {
    __shared__ float w1s[NGAUSS][HDIM];
    __shared__ float gs[S1ROWS][NGAUSS];
    const int blocksPerLayer = TTAB / S1ROWS;
    int l = blockIdx.x / blocksPerLayer;
    int t0 = (blockIdx.x % blocksPerLayer) * S1ROWS;
    const float* w1 = mlp_w1 + l * NGAUSS * HDIM;
    for (int i = threadIdx.x; i < NGAUSS * HDIM; i += blockDim.x)
        w1s[i / HDIM][i % HDIM] = w1[i];
    const float step = 10.0f / 49.0f;
    const float coeff = -0.5f / (step * step);
    for (int i = threadIdx.x; i < S1ROWS * NGAUSS; i += blockDim.x) {
        int r = i / NGAUSS, g = i % NGAUSS;
        float d = (float)(t0 + r) * (DCUT / (float)(TTAB - 1));
        float dd = d - (float)g * step;
        gs[r][g] = expf(coeff * dd * dd);
    }
    __syncthreads();
    int f = threadIdx.x;
    float b = mlp_b1[l * HDIM + f];
    #pragma unroll 1
    for (int r = 0; r < S1ROWS; r++) {
        float s = b;
        #pragma unroll
        for (int g = 0; g < NGAUSS; g++) s += gs[r][g] * w1s[g][f];
        U[(l * TTAB + t0 + r) * HDIM + f] = sspf(s);
    }
}

// ------------------- batched table GEMM: tab[l] = (U[l] @ w2[l] + b2[l]) * C(d) -------------------
// block tile 128x128, streams K in chunks of 32. grid = (TTAB/128, NLAYER).
__global__ void __launch_bounds__(256) k_tabgemm(
    const float* __restrict__ U, const float* __restrict__ w2all,
    const float* __restrict__ b2all, float* __restrict__ taball) {
    __shared__ float As[128][36];
    __shared__ float Bs[32][136];
    int tid = threadIdx.x;
    int lane = tid & 31, warp = tid >> 5;
    int gid = lane >> 2, tig = lane & 3;
    int warpM = warp & 3, warpN = warp >> 2;
    int layer = blockIdx.y;
    int row0 = blockIdx.x * 128;
    const float* A = U + (size_t)layer * TTAB * 128;
    const float* B = w2all + (size_t)layer * 128 * 128;
    const float* bias = b2all + layer * 128;
    float* C = taball + (size_t)layer * TTAB * 128;

    float c[2][8][4];
    #pragma unroll
    for (int mi = 0; mi < 2; mi++)
        #pragma unroll
        for (int nj = 0; nj < 8; nj++)
            #pragma unroll
            for (int q = 0; q < 4; q++) c[mi][nj][q] = 0.0f;

    for (int kc = 0; kc < 4; kc++) {
        if (kc) __syncthreads();
        #pragma unroll
        for (int i = 0; i < 4; i++) {
            int idx = tid + i * 256;
            int r = idx >> 3, c4 = (idx & 7) * 4;
            float4 v = *(const float4*)(A + (size_t)(row0 + r) * 128 + kc * 32 + c4);
            *(float4*)&As[r][c4] = v;
        }
        #pragma unroll
        for (int i = 0; i < 4; i++) {
            int idx = tid + i * 256;
            int r = idx >> 5, c4 = (idx & 31) * 4;
            *(float4*)&Bs[r][c4] = *(const float4*)(B + (size_t)(kc * 32 + r) * 128 + c4);
        }
        __syncthreads();
        #pragma unroll
        for (int ks = 0; ks < 4; ks++) {
            int k0 = ks * 8;
            unsigned a[2][4], b[8][2];
            #pragma unroll
            for (int mi = 0; mi < 2; mi++) {
                int mw = warpM * 32 + mi * 16 + gid;
                a[mi][0] = f2tf(As[mw][k0 + tig]);
                a[mi][1] = f2tf(As[mw + 8][k0 + tig]);
                a[mi][2] = f2tf(As[mw][k0 + tig + 4]);
                a[mi][3] = f2tf(As[mw + 8][k0 + tig + 4]);
            }
            #pragma unroll
            for (int nj = 0; nj < 8; nj++) {
                int nb = warpN * 64 + nj * 8 + gid;
                b[nj][0] = f2tf(Bs[k0 + tig][nb]);
                b[nj][1] = f2tf(Bs[k0 + tig + 4][nb]);
            }
            #pragma unroll
            for (int mi = 0; mi < 2; mi++)
                #pragma unroll
                for (int nj = 0; nj < 8; nj++) {
                    asm volatile(
                        "mma.sync.aligned.m16n8k8.row.col.f32.tf32.tf32.f32 "
                        "{%0,%1,%2,%3}, {%4,%5,%6,%7}, {%8,%9}, {%0,%1,%2,%3};"
                        : "+f"(c[mi][nj][0]), "+f"(c[mi][nj][1]),
                          "+f"(c[mi][nj][2]), "+f"(c[mi][nj][3])
                        : "r"(a[mi][0]), "r"(a[mi][1]), "r"(a[mi][2]), "r"(a[mi][3]),
                          "r"(b[nj][0]), "r"(b[nj][1]));
                }
        }
    }
    #pragma unroll
    for (int mi = 0; mi < 2; mi++) {
        #pragma unroll
        for (int half = 0; half < 2; half++) {
            int gr = row0 + warpM * 32 + mi * 16 + half * 8 + gid;
            float d = (float)gr * (DCUT / (float)(TTAB - 1));
            float Cc = 0.5f * (cosf(d * 0.31415926535897932f) + 1.0f);
            #pragma unroll
            for (int nj = 0; nj < 8; nj++) {
                int col = warpN * 64 + nj * 8 + tig * 2;
                float v0 = (c[mi][nj][half * 2 + 0] + bias[col]) * Cc;
                float v1 = (c[mi][nj][half * 2 + 1] + bias[col + 1]) * Cc;
                *(float2*)(C + (size_t)gr * 128 + col) = make_float2(v0, v1);
            }
        }
    }
}

// ------------------- fused GEMM chain: up to 4 back-to-back [M,128]x[128,128] -------------------
struct Stage {
    const float* B;
    const float* bias;
    const float* res;
    float* out;
    int ssp;
};

#define CHAIN_SMEM ((128 * 132 + 32 * 136) * 4)

__global__ void __launch_bounds__(256) k_chain(
    const float* __restrict__ A0, int M, int nstages,
    Stage s0, Stage s1, Stage s2, Stage s3) {
    extern __shared__ float smem[];
    float* As = smem;                 // [128][132]
    float* Bs = smem + 128 * 132;     // [32][136]
    int tid = threadIdx.x;
    int lane = tid & 31, warp = tid >> 5;
    int gid = lane >> 2, tig = lane & 3;
    int warpM = warp & 3, warpN = warp >> 2;
    int row0 = blockIdx.x * 128;

    // load A0 into As (zero OOB rows)
    #pragma unroll
    for (int i = 0; i < 8; i++) {
        int idx = tid + i * 256;      // 0..2047 -> 128 rows x 32 float4
        int r = idx >> 4, c4 = (idx & 15) * 8;
        float4 v0 = make_float4(0.f, 0.f, 0.f, 0.f), v1 = v0;
        int gr = row0 + r;
        if (gr < M) {
            v0 = *(const float4*)(A0 + (size_t)gr * 128 + c4);
            v1 = *(const float4*)(A0 + (size_t)gr * 128 + c4 + 4);
        }
        *(float4*)&As[r * 132 + c4] = v0;
        *(float4*)&As[r * 132 + c4 + 4] = v1;
    }
    __syncthreads();

    Stage st[4] = {s0, s1, s2, s3};
    #pragma unroll 1
    for (int s = 0; s < nstages; s++) {
        const float* B = st[s].B;
        float c[2][8][4];
        #pragma unroll
        for (int mi = 0; mi < 2; mi++)
            #pragma unroll
            for (int nj = 0; nj < 8; nj++)
                #pragma unroll
                for (int q = 0; q < 4; q++) c[mi][nj][q] = 0.0f;

        #pragma unroll 1
        for (int kc = 0; kc < 4; kc++) {
            #pragma unroll
            for (int i = 0; i < 4; i++) {
                int idx = tid + i * 256;
                int r = idx >> 5, c4 = (idx & 31) * 4;
                *(float4*)&Bs[r * 136 + c4] =
                    *(const float4*)(B + (size_t)(kc * 32 + r) * 128 + c4);
            }
            __syncthreads();
            #pragma unroll
            for (int ks = 0; ks < 4; ks++) {
                int k0 = kc * 32 + ks * 8;
                int kb = ks * 8;
                unsigned a[2][4], b[8][2];
                #pragma unroll
                for (int mi = 0; mi < 2; mi++) {
                    int mw = warpM * 32 + mi * 16 + gid;
                    a[mi][0] = f2tf(As[mw * 132 + k0 + tig]);
                    a[mi][1] = f2tf(As[(mw + 8) * 132 + k0 + tig]);
                    a[mi][2] = f2tf(As[mw * 132 + k0 + tig + 4]);
                    a[mi][3] = f2tf(As[(mw + 8) * 132 + k0 + tig + 4]);
                }
                #pragma unroll
                for (int nj = 0; nj < 8; nj++) {
                    int nb = warpN * 64 + nj * 8 + gid;
                    b[nj][0] = f2tf(Bs[(kb + tig) * 136 + nb]);
                    b[nj][1] = f2tf(Bs[(kb + tig + 4) * 136 + nb]);
                }
                #pragma unroll
                for (int mi = 0; mi < 2; mi++)
                    #pragma unroll
                    for (int nj = 0; nj < 8; nj++) {
                        asm volatile(
                            "mma.sync.aligned.m16n8k8.row.col.f32.tf32.tf32.f32 "
                            "{%0,%1,%2,%3}, {%4,%5,%6,%7}, {%8,%9}, {%0,%1,%2,%3};"
                            : "+f"(c[mi][nj][0]), "+f"(c[mi][nj][1]),
                              "+f"(c[mi][nj][2]), "+f"(c[mi][nj][3])
                            : "r"(a[mi][0]), "r"(a[mi][1]), "r"(a[mi][2]), "r"(a[mi][3]),
                              "r"(b[nj][0]), "r"(b[nj][1]));
                    }
            }
            __syncthreads();
        }
        // epilogue
        const float* bias = st[s].bias;
        const float* res = st[s].res;
        float* out = st[s].out;
        int doSSP = st[s].ssp;
        int keep = (s < nstages - 1);
        #pragma unroll
        for (int mi = 0; mi < 2; mi++) {
            #pragma unroll
            for (int half = 0; half < 2; half++) {
                int lr = warpM * 32 + mi * 16 + half * 8 + gid;
                int gr = row0 + lr;
                #pragma unroll
                for (int nj = 0; nj < 8; nj++) {
                    int col = warpN * 64 + nj * 8 + tig * 2;
                    float v0 = 0.0f, v1 = 0.0f;
                    if (gr < M) {
                        v0 = c[mi][nj][half * 2 + 0];
                        v1 = c[mi][nj][half * 2 + 1];
                        if (bias) { v0 += bias[col]; v1 += bias[col + 1]; }
                        if (doSSP) { v0 = sspf(v0); v1 = sspf(v1); }
                        if (res) {
                            float2 rr = *(const float2*)(res + (size_t)gr * 128 + col);
                            v0 += rr.x; v1 += rr.y;
                        }
                        if (out)
                            *(float2*)(out + (size_t)gr * 128 + col) = make_float2(v0, v1);
                    }
                    if (keep)
                        *(float2*)&As[lr * 132 + col] = make_float2(v0, v1);
                }
            }
        }
        if (keep) __syncthreads();
    }
}

// ------------------- edge aggregation: warp per node, lerp W from table -------------------
__global__ void k_edge(const int* __restrict__ rowptr, const int* __restrict__ src,
                       const float* __restrict__ et, const float* __restrict__ xf,
                       const float* __restrict__ tab, float* __restrict__ agg) {
    int node = blockIdx.x * 8 + (threadIdx.x >> 5);
    if (node >= NATOMS) return;
    int lane = threadIdx.x & 31;
    int s = rowptr[node], e = rowptr[node + 1];
    float4 acc = make_float4(0.f, 0.f, 0.f, 0.f);
    for (int p = s; p < e; p++) {
        int j = __ldg(&src[p]);
        float t = __ldg(&et[p]);
        int i0 = (int)t;
        float fr = t - (float)i0;
        float4 x  = *(const float4*)(xf  + (size_t)j * 128 + lane * 4);
        float4 w0 = *(const float4*)(tab + (size_t)i0 * 128 + lane * 4);
        float4 w1 = *(const float4*)(tab + (size_t)i0 * 128 + 128 + lane * 4);
        acc.x += x.x * (w0.x + fr * (w1.x - w0.x));
        acc.y += x.y * (w0.y + fr * (w1.y - w0.y));
        acc.z += x.z * (w0.z + fr * (w1.z - w0.z));
        acc.w += x.w * (w0.w + fr * (w1.w - w0.w));
    }
    *(float4*)(agg + (size_t)node * 128 + lane * 4) = acc;
}

// ------------------- molecule pooling (atom_to_conf sorted -> run-length) -------------------
#define MCHUNK 256
__global__ void k_molsum(const float* __restrict__ h2, const int* __restrict__ a2c,
                         const int* __restrict__ c2m, float* __restrict__ mol) {
    int f = threadIdx.x;  // 128
    int a0 = blockIdx.x * MCHUNK;
    int aend = min(a0 + MCHUNK, NATOMS);
    int curm = -1;
    float acc = 0.0f;
    for (int a = a0; a < aend; a++) {
        int m = __ldg(&c2m[__ldg(&a2c[a])]);
        if (m != curm) {
            if (curm >= 0) atomicAdd(&mol[curm * 128 + f], acc);
            curm = m;
            acc = 0.0f;
        }
        acc += h2[(size_t)a * 128 + f];
    }
    if (curm >= 0) atomicAdd(&mol[curm * 128 + f], acc);
}

// ------------------- head MLP -------------------
__global__ void k_head(const float* __restrict__ mol, const float* __restrict__ w1,
                       const float* __restrict__ b1, const float* __restrict__ w2,
                       const float* __restrict__ b2, float* __restrict__ out) {
    __shared__ float red[64];
    int m = blockIdx.x;
    int j = threadIdx.x;  // 64
    float s = b1[j];
    for (int f = 0; f < 128; f++) s += mol[m * 128 + f] * w1[f * 64 + j];
    red[j] = sspf(s) * w2[j];
    __syncthreads();
    for (int off = 32; off > 0; off >>= 1) {
        if (j < off) red[j] += red[j + off];
        __syncthreads();
    }
    if (j == 0) out[m] = red[0] + b2[0];
}

// ------------------- launch -------------------
extern "C" void kernel_launch(void* const* d_in, const int* in_sizes, int n_in,
                              void* d_out, int out_size) {
    const int*   z     = (const int*)d_in[0];
    const float* pos   = (const float*)d_in[1];
    const int*   erow  = (const int*)d_in[2];
    const int*   ecol  = (const int*)d_in[3];
    const int*   a2c   = (const int*)d_in[4];
    const int*   c2m   = (const int*)d_in[5];
    const float* emb   = (const float*)d_in[6];
    const float* mw1   = (const float*)d_in[7];
    const float* mb1   = (const float*)d_in[8];
    const float* mw2   = (const float*)d_in[9];
    const float* mb2   = (const float*)d_in[10];
    const float* cl1w  = (const float*)d_in[11];
    const float* cl2w  = (const float*)d_in[12];
    const float* cl2b  = (const float*)d_in[13];
    const float* ilw   = (const float*)d_in[14];
    const float* ilb   = (const float*)d_in[15];
    const float* l1w   = (const float*)d_in[16];
    const float* l1b   = (const float*)d_in[17];
    const float* l2w   = (const float*)d_in[18];
    const float* l2b   = (const float*)d_in[19];
    const float* hw1   = (const float*)d_in[20];
    const float* hb1   = (const float*)d_in[21];
    const float* hw2   = (const float*)d_in[22];
    const float* hb2   = (const float*)d_in[23];
    float* out = (float*)d_out;

    float *ph, *pxf, *pagg, *pU, *ptab, *pt, *pet, *pmol;
    int *pcnt, *prow, *pcur, *psrc;
    cudaGetSymbolAddress((void**)&ph, g_h);
    cudaGetSymbolAddress((void**)&pxf, g_xf);
    cudaGetSymbolAddress((void**)&pagg, g_agg);
    cudaGetSymbolAddress((void**)&pU, g_U);
    cudaGetSymbolAddress((void**)&ptab, g_tab);
    cudaGetSymbolAddress((void**)&pt, g_t);
    cudaGetSymbolAddress((void**)&pet, g_et);
    cudaGetSymbolAddress((void**)&pcnt, g_cnt);
    cudaGetSymbolAddress((void**)&prow, g_rowptr);
    cudaGetSymbolAddress((void**)&pcur, g_cursor);
    cudaGetSymbolAddress((void**)&psrc, g_src);
    cudaGetSymbolAddress((void**)&pmol, g_mol);

    cudaFuncSetAttribute(k_chain, cudaFuncAttributeMaxDynamicSharedMemorySize, CHAIN_SMEM);

    cudaMemsetAsync(pcnt, 0, NATOMS * sizeof(int));
    cudaMemsetAsync(pmol, 0, NMOL * HDIM * sizeof(float));

    Stage Z = {nullptr, nullptr, nullptr, nullptr, 0};

    // embedding
    k_embed<<<(NATOMS * HDIM + 255) / 256, 256>>>(z, emb, ph);
    // graph preprocessing
    k_dist<<<(NEDGE + 255) / 256, 256>>>(pos, erow, ecol, pt, pcnt);
    k_scan<<<1, 1024>>>(pcnt, prow, pcur);
    k_fill<<<(NEDGE + 255) / 256, 256>>>(erow, ecol, pt, pcur, psrc, pet);
    // filter tables: stage1 + batched GEMM (cosine folded into epilogue)
    k_stage1<<<NLAYER * (TTAB / S1ROWS), 128>>>(mw1, mb1, pU);
    k_tabgemm<<<dim3(TTAB / 128, NLAYER), 256>>>(pU, mw2, mb2, ptab);

    const int blocks = (NATOMS + 127) / 128;
    // xf0 = h @ cl1w[0]
    {
        Stage a = {cl1w, nullptr, nullptr, pxf, 0};
        k_chain<<<blocks, 256, CHAIN_SMEM>>>(ph, NATOMS, 1, a, Z, Z, Z);
    }
    for (int l = 0; l < NLAYER - 1; l++) {
        k_edge<<<(NATOMS + 7) / 8, 256>>>(prow, psrc, pet, pxf,
                                          ptab + (size_t)l * TTAB * 128, pagg);
        Stage a = {cl2w + l * 128 * 128, cl2b + l * 128, nullptr, nullptr, 1};
        Stage b = {ilw + l * 128 * 128, ilb + l * 128, ph, ph, 0};
        Stage cst = {cl1w + (l + 1) * 128 * 128, nullptr, nullptr, pxf, 0};
        k_chain<<<blocks, 256, CHAIN_SMEM>>>(pagg, NATOMS, 3, a, b, cst, Z);
    }
    // layer 5 + final node MLP fused (4 stages)
    {
        int l = NLAYER - 1;
        k_edge<<<(NATOMS + 7) / 8, 256>>>(prow, psrc, pet, pxf,
                                          ptab + (size_t)l * TTAB * 128, pagg);
        Stage a = {cl2w + l * 128 * 128, cl2b + l * 128, nullptr, nullptr, 1};
        Stage b = {ilw + l * 128 * 128, ilb + l * 128, ph, nullptr, 0};
        Stage cst = {l1w, l1b, nullptr, nullptr, 1};
        Stage d = {l2w, l2b, nullptr, pxf, 0};
        k_chain<<<blocks, 256, CHAIN_SMEM>>>(pagg, NATOMS, 4, a, b, cst, d);
    }
    // pooling + head (h2 lives in pxf)
    k_molsum<<<(NATOMS + MCHUNK - 1) / MCHUNK, 128>>>(pxf, a2c, c2m, pmol);
    k_head<<<NMOL, 64>>>(pmol, hw1, hb1, hw2, hb2, out);
}